// round 15
// baseline (speedup 1.0000x reference)
#include <cuda_runtime.h>
#include <cuda_fp16.h>
#include <math.h>
#include <stdint.h>

// Problem constants
#define BB 2
#define SS 2048
#define HH 1024
#define NHH 16
#define MM (BB * SS)   // 4096
#define SQKV 3072

#define NEGF (-1e30f)
#define QSCALE 0.1803368801f   // 0.125 * log2(e)

// Scratch (device globals)
__device__ __half g_QKVh[MM * SQKV];
__device__ __half g_AOh[MM * HH];
__device__ __half g_Wqkvh[SQKV * HH];
__device__ __half g_WOh[HH * HH];
__device__ float  g_bqkv[SQKV];

// ---------------------------------------------------------------------------
// helpers
// ---------------------------------------------------------------------------
__device__ __forceinline__ uint32_t smem_u32(const void* p) {
    uint32_t a;
    asm("{ .reg .u64 t; cvta.to.shared.u64 t, %1; cvt.u32.u64 %0, t; }"
        : "=r"(a) : "l"(p));
    return a;
}

__device__ __forceinline__ void ldsm_x4(uint32_t* r, uint32_t addr) {
    asm volatile("ldmatrix.sync.aligned.m8n8.x4.shared.b16 {%0,%1,%2,%3}, [%4];"
                 : "=r"(r[0]), "=r"(r[1]), "=r"(r[2]), "=r"(r[3]) : "r"(addr));
}
__device__ __forceinline__ void ldsm_x4t(uint32_t* r, uint32_t addr) {
    asm volatile("ldmatrix.sync.aligned.m8n8.x4.trans.shared.b16 {%0,%1,%2,%3}, [%4];"
                 : "=r"(r[0]), "=r"(r[1]), "=r"(r[2]), "=r"(r[3]) : "r"(addr));
}
__device__ __forceinline__ void mma_f16(float* c, const uint32_t* a, const uint32_t* b) {
    asm volatile(
        "mma.sync.aligned.m16n8k16.row.col.f32.f16.f16.f32 "
        "{%0,%1,%2,%3}, {%4,%5,%6,%7}, {%8,%9}, {%0,%1,%2,%3};"
        : "+f"(c[0]), "+f"(c[1]), "+f"(c[2]), "+f"(c[3])
        : "r"(a[0]), "r"(a[1]), "r"(a[2]), "r"(a[3]), "r"(b[0]), "r"(b[1]));
}

#define CP16(smaddr, gptr) \
    asm volatile("cp.async.cg.shared.global [%0], [%1], 16;" \
                 :: "r"(smaddr), "l"(gptr) : "memory")
#define CP_COMMIT() asm volatile("cp.async.commit_group;" ::: "memory")
#define CP_WAIT2() asm volatile("cp.async.wait_group 2;" ::: "memory")
#define CP_WAIT1() asm volatile("cp.async.wait_group 1;" ::: "memory")
#define CP_WAIT0() asm volatile("cp.async.wait_group 0;" ::: "memory")

__device__ __forceinline__ uint32_t pack1(float x, float y) {
    __half2 h = __floats2half2_rn(x, y);
    return *(uint32_t*)&h;
}

// ---------------------------------------------------------------------------
// 4-way transpose 1024x1024 fp32 -> fp16, out[n][k] = W[k][n]; also packs
// the QKV bias vector (z<3 blocks copy their bias chunk).
// ---------------------------------------------------------------------------
__global__ __launch_bounds__(256) void transpose_half4(
    const float* __restrict__ W0, const float* __restrict__ W1,
    const float* __restrict__ W2, const float* __restrict__ W3,
    const float* __restrict__ b0, const float* __restrict__ b1,
    const float* __restrict__ b2,
    __half* __restrict__ qkvh, __half* __restrict__ woh,
    float* __restrict__ bqkv)
{
    __shared__ float t[32][33];
    const int z = blockIdx.z;
    const float* W = (z == 0) ? W0 : (z == 1) ? W1 : (z == 2) ? W2 : W3;
    __half* ho = (z < 3) ? qkvh + (size_t)z * HH * HH : woh;
    const int tid = threadIdx.y * 32 + threadIdx.x;

    if (z < 3 && blockIdx.x == 0 && blockIdx.y == 0) {
        const float* bz = (z == 0) ? b0 : (z == 1) ? b1 : b2;
        for (int i = tid; i < HH; i += 256) bqkv[z * HH + i] = bz[i];
    }

    int x = blockIdx.x * 32 + threadIdx.x;
    int y = blockIdx.y * 32 + threadIdx.y;
#pragma unroll
    for (int j = 0; j < 32; j += 8)
        t[threadIdx.y + j][threadIdx.x] = W[(size_t)(y + j) * HH + x];
    __syncthreads();
    x = blockIdx.y * 32 + threadIdx.x;
    y = blockIdx.x * 32 + threadIdx.y;
#pragma unroll
    for (int j = 0; j < 32; j += 8)
        ho[(size_t)(y + j) * HH + x] = __float2half_rn(t[threadIdx.x][threadIdx.y + j]);
}

// ---------------------------------------------------------------------------
// fp16 tensor-core GEMM: C[M=4096, NOUT] = A[M,1024] @ BT[NOUT,1024]^T + bias
// 3-stage cp.async pipeline: compute of chunk k overlaps loads of k+1, k+2.
// ---------------------------------------------------------------------------
#define GK 1024
#define KC 32
#define LDAe 40
#define TILE_B (128 * LDAe * 2)
#define STAGE_B (2 * TILE_B)
#define GEMM_SMEM (3 * STAGE_B)   // 61440

template<bool HALF_OUT, bool QPRESCALE, bool A32>
__global__ __launch_bounds__(256, 2) void gemm_f16_kernel(
    const void* __restrict__ Ap, const __half* __restrict__ Bh,
    const float* __restrict__ bias, int NOUT, float* __restrict__ C,
    __half* __restrict__ Ch)
{
    extern __shared__ char sm[];
    const uint32_t sbase = smem_u32(sm);
    const int tid = threadIdx.x;
    const int wid = tid >> 5;
    const int lane = tid & 31;
    const int n0 = blockIdx.x * 128;
    const int m0 = blockIdx.y * 128;
    const int wm = (wid & 3) * 32;
    const int wn = (wid >> 2) * 64;

    const float* A32p = (const float*)Ap;
    const __half* A16p = (const __half*)Ap;

    float acc[2][8][4];
#pragma unroll
    for (int mi = 0; mi < 2; mi++)
#pragma unroll
        for (int ni = 0; ni < 8; ni++)
#pragma unroll
            for (int j = 0; j < 4; j++) acc[mi][ni][j] = 0.f;

    const int lr0 = tid >> 2;
    const int lc0 = tid & 3;

    float4 areg[2][2];

    auto ldgA = [&](int kc) {
        const int kk = kc * KC;
#pragma unroll
        for (int s = 0; s < 2; s++) {
            const int row = lr0 + s * 64;
            const float* p = A32p + (size_t)(m0 + row) * GK + kk + lc0 * 8;
            areg[s][0] = *(const float4*)p;
            areg[s][1] = *(const float4*)(p + 4);
        }
    };
    auto stsA = [&](int stage) {
#pragma unroll
        for (int s = 0; s < 2; s++) {
            const int row = lr0 + s * 64;
            uint4 v;
            v.x = pack1(areg[s][0].x, areg[s][0].y);
            v.y = pack1(areg[s][0].z, areg[s][0].w);
            v.z = pack1(areg[s][1].x, areg[s][1].y);
            v.w = pack1(areg[s][1].z, areg[s][1].w);
            *(uint4*)(sm + stage * STAGE_B + row * (LDAe * 2) + lc0 * 16) = v;
        }
    };
    auto cpB = [&](int kc, int stage) {
        const int kk = kc * KC;
        const uint32_t sb = sbase + stage * STAGE_B;
#pragma unroll
        for (int s = 0; s < 2; s++) {
            const int row = lr0 + s * 64;
            CP16(sb + TILE_B + (uint32_t)(row * (LDAe * 2) + lc0 * 16),
                 Bh + (size_t)(n0 + row) * GK + kk + lc0 * 8);
        }
    };
    auto cpA16 = [&](int kc, int stage) {
        const int kk = kc * KC;
        const uint32_t sb = sbase + stage * STAGE_B;
#pragma unroll
        for (int s = 0; s < 2; s++) {
            const int row = lr0 + s * 64;
            CP16(sb + (uint32_t)(row * (LDAe * 2) + lc0 * 16),
                 A16p + (size_t)(m0 + row) * GK + kk + lc0 * 8);
        }
    };

    const int NC = GK / KC;   // 32
    // prologue: fill stages 0 and 1; prefetch A regs for chunk 2
    if (A32) {
        ldgA(0); stsA(0); cpB(0, 0); CP_COMMIT();
        ldgA(1); stsA(1); cpB(1, 1); CP_COMMIT();
        ldgA(2);
    } else {
        cpA16(0, 0); cpB(0, 0); CP_COMMIT();
        cpA16(1, 1); cpB(1, 1); CP_COMMIT();
    }

    for (int kc = 0; kc < NC; kc++) {
        const int stage = kc % 3;
        if (kc + 2 < NC) {
            const int nst = (kc + 2) % 3;
            if (A32) {
                stsA(nst);                 // uses areg of chunk kc+2
                cpB(kc + 2, nst);
                CP_COMMIT();
                if (kc + 3 < NC) ldgA(kc + 3);
            } else {
                cpA16(kc + 2, nst);
                cpB(kc + 2, nst);
                CP_COMMIT();
            }
            CP_WAIT2();
        } else if (kc + 1 < NC) {
            CP_WAIT1();
        } else {
            CP_WAIT0();
        }
        __syncthreads();

        const uint32_t sb = sbase + stage * STAGE_B;
#pragma unroll
        for (int k16 = 0; k16 < KC; k16 += 16) {
            uint32_t ah[2][4];
#pragma unroll
            for (int mi = 0; mi < 2; mi++) {
                uint32_t addr = sb + 2u * (uint32_t)(
                    (wm + mi * 16 + (lane & 15)) * LDAe + k16 + 8 * (lane >> 4));
                ldsm_x4(ah[mi], addr);
            }
#pragma unroll
            for (int ni = 0; ni < 8; ni += 2) {
                const int mt = lane >> 3;
                const int rowB = wn + (ni + (mt >> 1)) * 8 + (lane & 7);
                uint32_t baddr = sb + TILE_B + 2u * (uint32_t)(
                    rowB * LDAe + k16 + 8 * (mt & 1));
                uint32_t bh[4];
                ldsm_x4(bh, baddr);
#pragma unroll
                for (int mi = 0; mi < 2; mi++) {
                    mma_f16(acc[mi][ni],     ah[mi], bh);
                    mma_f16(acc[mi][ni + 1], ah[mi], bh + 2);
                }
            }
        }
        __syncthreads();
    }

#pragma unroll
    for (int mi = 0; mi < 2; mi++) {
#pragma unroll
        for (int ni = 0; ni < 8; ni++) {
            const int m = m0 + wm + mi * 16 + (lane >> 2);
            const int n = n0 + wn + ni * 8 + 2 * (lane & 3);
            const float b0 = bias[n], b1 = bias[n + 1];
            float sc = (QPRESCALE && n < 1024) ? QSCALE : 1.0f;
            float x0 = (acc[mi][ni][0] + b0) * sc, y0 = (acc[mi][ni][1] + b1) * sc;
            float x1 = (acc[mi][ni][2] + b0) * sc, y1 = (acc[mi][ni][3] + b1) * sc;
            if (HALF_OUT) {
                *(uint32_t*)(Ch + (size_t)m * NOUT + n) = pack1(x0, y0);
                *(uint32_t*)(Ch + (size_t)(m + 8) * NOUT + n) = pack1(x1, y1);
            } else {
                *(float2*)(C + (size_t)m * NOUT + n) = make_float2(x0, y0);
                *(float2*)(C + (size_t)(m + 8) * NOUT + n) = make_float2(x1, y1);
            }
        }
    }
}

// ---------------------------------------------------------------------------
// Tensor-core flash attention (unchanged from round 14).
// ---------------------------------------------------------------------------
#define ARS 144                       // row stride bytes (64 halfs + 8 pad)
#define AKV (64 * ARS)                // 9216 per K or V tile
#define APADF (2 * AKV)               // pad floats at stage +18432
#define APFLG (APADF + 256)           // pad flag (int) per stage
#define AST_SZ (2 * AKV + 512)        // 18944
#define ATT_SMEM (2 * AST_SZ)         // 37888

__global__ __launch_bounds__(128, 3) void flash_attn_tc_kernel(
    const __half* __restrict__ QKVh, const int* __restrict__ ids,
    __half* __restrict__ AOh)
{
    extern __shared__ char sm[];
    const uint32_t sb = smem_u32(sm);
    const int tid = threadIdx.x;
    const int wid = tid >> 5;
    const int lane = tid & 31;
    const int qt = 15 - blockIdx.x;       // heavy tiles first
    const int q0 = qt * 128;
    const int h  = blockIdx.y;
    const int b  = blockIdx.z;
    const int wr = wid * 32;              // 32 q-rows per warp
    const int r4 = lane >> 2;
    const int c2 = lane & 3;

    // ---- load Q tile (128 rows) into smem (spans both stages), to regs ----
    {
        const size_t qbase = (size_t)(b * SS + q0) * SQKV + h * 64;
#pragma unroll
        for (int i = 0; i < 8; i++) {
            int idx = tid + i * 128;
            int row = idx >> 3, c8 = idx & 7;
            CP16(sb + (uint32_t)(row * ARS + c8 * 16),
                 QKVh + qbase + (size_t)row * SQKV + c8 * 8);
        }
        CP_COMMIT();
    }
    CP_WAIT0();
    __syncthreads();

    uint32_t aq[2][4][4];   // [m-frag][k16][regs]
#pragma unroll
    for (int mi = 0; mi < 2; mi++) {
        const uint32_t abase = sb + (uint32_t)((wr + mi * 16 + (lane & 15)) * ARS
                                               + (lane >> 4) * 16);
#pragma unroll
        for (int k16 = 0; k16 < 4; k16++)
            ldsm_x4(aq[mi][k16], abase + k16 * 32);
    }
    __syncthreads();   // everyone done reading Q before K/V overwrite

    float* padp[2] = { (float*)(sm + APADF), (float*)(sm + AST_SZ + APADF) };
    int* flagp[2]  = { (int*)(sm + APFLG),   (int*)(sm + AST_SZ + APFLG) };

    auto issue_tile = [&](int kt, int stage) {
        const int k0 = kt * 64;
        const uint32_t st = sb + stage * AST_SZ;
#pragma unroll
        for (int i = 0; i < 4; i++) {
            int idx = tid + i * 128;
            int row = idx >> 3, c8 = idx & 7;   // row 0..63
            uint32_t off = (uint32_t)(row * ARS + c8 * 16);
            size_t gk = (size_t)(b * SS + k0 + row) * SQKV + h * 64 + 1024 + c8 * 8;
            CP16(st + off,       QKVh + gk);           // K
            CP16(st + AKV + off, QKVh + gk + 1024);    // V
        }
        if (tid < 32) {  // single warp: race-free pad flag via ballot
            int p0 = (ids[b * SS + k0 + tid] == 0);
            int p1 = (ids[b * SS + k0 + 32 + tid] == 0);
            padp[stage][tid]      = p0 ? NEGF : 0.f;
            padp[stage][32 + tid] = p1 ? NEGF : 0.f;
            uint32_t any = __ballot_sync(0xffffffffu, p0 | p1);
            if (tid == 0) flagp[stage][0] = (any != 0);
        }
        CP_COMMIT();
    };

    issue_tile(0, 0);

    float o[2][8][4];
#pragma unroll
    for (int mi = 0; mi < 2; mi++)
#pragma unroll
        for (int nb = 0; nb < 8; nb++)
#pragma unroll
            for (int j = 0; j < 4; j++) o[mi][nb][j] = 0.f;
    float lr[2][2] = {{0.f, 0.f}, {0.f, 0.f}};   // [m-frag][row-half]

    const int qmax = q0 + wr + 31;        // warp's last q row
    const int nkt = 2 * qt + 2;           // 64-key tiles up to q0+127

    for (int kt = 0; kt < nkt; kt++) {
        const int stage = kt & 1;
        const int k0 = kt * 64;
        if (kt + 1 < nkt) { issue_tile(kt + 1, stage ^ 1); CP_WAIT1(); }
        else              { CP_WAIT0(); }
        __syncthreads();

        if (k0 <= qmax) {
            const uint32_t sth = sb + stage * AST_SZ;
            const float* padf = padp[stage];
            const bool haspad = (flagp[stage][0] != 0);
            const int mt = lane >> 3;

            // process 16-key chunks
#pragma unroll
            for (int c = 0; c < 4; c++) {
                const int k0c = k0 + c * 16;
                if (k0c > qmax) break;

                // ---- S chunk = Q K^T ----
                float s[2][2][4];
#pragma unroll
                for (int mi = 0; mi < 2; mi++)
#pragma unroll
                    for (int bbh = 0; bbh < 2; bbh++)
#pragma unroll
                        for (int j = 0; j < 4; j++) s[mi][bbh][j] = 0.f;

                const uint32_t bbase = sth + (uint32_t)(
                    (c * 16 + (mt >> 1) * 8 + (lane & 7)) * ARS + (mt & 1) * 16);
#pragma unroll
                for (int k16 = 0; k16 < 4; k16++) {
                    uint32_t bh[4];
                    ldsm_x4(bh, bbase + k16 * 32);
#pragma unroll
                    for (int mi = 0; mi < 2; mi++) {
                        mma_f16(s[mi][0], aq[mi][k16], bh);
                        mma_f16(s[mi][1], aq[mi][k16], bh + 2);
                    }
                }

                // ---- softmax: fast path (no mask) or full path ----
                const bool need_causal = (k0c + 15 > q0 + wr);
                if (!need_causal && !haspad) {
#pragma unroll
                    for (int mi = 0; mi < 2; mi++)
#pragma unroll
                        for (int bbh = 0; bbh < 2; bbh++) {
                            float v0 = exp2f(s[mi][bbh][0]);
                            float v1 = exp2f(s[mi][bbh][1]);
                            float v2 = exp2f(s[mi][bbh][2]);
                            float v3 = exp2f(s[mi][bbh][3]);
                            s[mi][bbh][0] = v0; s[mi][bbh][1] = v1;
                            s[mi][bbh][2] = v2; s[mi][bbh][3] = v3;
                            lr[mi][0] += v0 + v1;
                            lr[mi][1] += v2 + v3;
                        }
                } else {
#pragma unroll
                    for (int mi = 0; mi < 2; mi++) {
                        const int qg = q0 + wr + mi * 16 + r4;
#pragma unroll
                        for (int bbh = 0; bbh < 2; bbh++) {
                            const int col = c * 16 + bbh * 8 + 2 * c2;
                            const float p0 = padf[col], p1 = padf[col + 1];
                            float v0 = s[mi][bbh][0] + p0;
                            float v1 = s[mi][bbh][1] + p1;
                            float v2 = s[mi][bbh][2] + p0;
                            float v3 = s[mi][bbh][3] + p1;
                            if (need_causal) {
                                const int kg = k0 + col;
                                if (kg     > qg)     v0 = NEGF;
                                if (kg + 1 > qg)     v1 = NEGF;
                                if (kg     > qg + 8) v2 = NEGF;
                                if (kg + 1 > qg + 8) v3 = NEGF;
                            }
                            v0 = exp2f(v0); v1 = exp2f(v1);
                            v2 = exp2f(v2); v3 = exp2f(v3);
                            s[mi][bbh][0] = v0; s[mi][bbh][1] = v1;
                            s[mi][bbh][2] = v2; s[mi][bbh][3] = v3;
                            lr[mi][0] += v0 + v1;
                            lr[mi][1] += v2 + v3;
                        }
                    }
                }

                // ---- pack P ----
                uint32_t ph[2][4];
#pragma unroll
                for (int mi = 0; mi < 2; mi++) {
                    ph[mi][0] = pack1(s[mi][0][0], s[mi][0][1]);
                    ph[mi][1] = pack1(s[mi][0][2], s[mi][0][3]);
                    ph[mi][2] = pack1(s[mi][1][0], s[mi][1][1]);
                    ph[mi][3] = pack1(s[mi][1][2], s[mi][1][3]);
                }

                // ---- O += P V (chunk rows of V) ----
                const uint32_t vbase = sth + AKV + (uint32_t)(
                    (c * 16 + (lane & 15)) * ARS + (lane >> 4) * 16);
#pragma unroll
                for (int nb = 0; nb < 8; nb += 2) {
                    uint32_t vh_[4];
                    ldsm_x4t(vh_, vbase + (uint32_t)(nb * 16));
#pragma unroll
                    for (int mi = 0; mi < 2; mi++) {
                        mma_f16(o[mi][nb],     ph[mi], vh_);
                        mma_f16(o[mi][nb + 1], ph[mi], vh_ + 2);
                    }
                }
            }
        }
        __syncthreads();
    }

    // ---- epilogue: reduce l across the 4-lane row group, normalize ----
#pragma unroll
    for (int mi = 0; mi < 2; mi++)
#pragma unroll
        for (int hh = 0; hh < 2; hh++)
#pragma unroll
            for (int off = 1; off < 4; off <<= 1)
                lr[mi][hh] += __shfl_xor_sync(0xffffffffu, lr[mi][hh], off);

#pragma unroll
    for (int mi = 0; mi < 2; mi++) {
        const float il0 = 1.f / lr[mi][0];
        const float il1 = 1.f / lr[mi][1];
        const int qg = q0 + wr + mi * 16 + r4;
        const size_t r0off = (size_t)(b * SS + qg) * HH + h * 64;
        const size_t r1off = r0off + (size_t)8 * HH;
#pragma unroll
        for (int nb = 0; nb < 8; nb++) {
            const int n = 8 * nb + 2 * c2;
            *(uint32_t*)(AOh + r0off + n) = pack1(o[mi][nb][0] * il0, o[mi][nb][1] * il0);
            *(uint32_t*)(AOh + r1off + n) = pack1(o[mi][nb][2] * il1, o[mi][nb][3] * il1);
        }
    }
}

// ---------------------------------------------------------------------------

extern "C" void kernel_launch(void* const* d_in, const int* in_sizes, int n_in,
                              void* d_out, int out_size)
{
    const float* X   = (const float*)d_in[0];
    const int*   ids = (const int*)d_in[1];
    const float* WQ  = (const float*)d_in[2];
    const float* WK  = (const float*)d_in[3];
    const float* WV  = (const float*)d_in[4];
    const float* bQ  = (const float*)d_in[5];
    const float* bK  = (const float*)d_in[6];
    const float* bV  = (const float*)d_in[7];
    const float* WO  = (const float*)d_in[8];
    const float* bO  = (const float*)d_in[9];
    float* out = (float*)d_out;

    __half *pQKVh, *pAOh, *pWqkvh, *pWOh;
    float* pbqkv;
    cudaGetSymbolAddress((void**)&pQKVh,  g_QKVh);
    cudaGetSymbolAddress((void**)&pAOh,   g_AOh);
    cudaGetSymbolAddress((void**)&pWqkvh, g_Wqkvh);
    cudaGetSymbolAddress((void**)&pWOh,   g_WOh);
    cudaGetSymbolAddress((void**)&pbqkv,  g_bqkv);

    dim3 tgrid(32, 32, 4), tblk(32, 8);
    transpose_half4<<<tgrid, tblk>>>(WQ, WK, WV, WO, bQ, bK, bV,
                                     pWqkvh, pWOh, pbqkv);

    cudaFuncSetAttribute((const void*)gemm_f16_kernel<true, true, true>,
                         cudaFuncAttributeMaxDynamicSharedMemorySize, GEMM_SMEM);
    cudaFuncSetAttribute((const void*)gemm_f16_kernel<false, false, false>,
                         cudaFuncAttributeMaxDynamicSharedMemorySize, GEMM_SMEM);

    dim3 qkvgrid(SQKV / 128, MM / 128);   // (24, 32)
    gemm_f16_kernel<true, true, true><<<qkvgrid, 256, GEMM_SMEM>>>(
        X, pWqkvh, pbqkv, SQKV, nullptr, pQKVh);

    cudaFuncSetAttribute(flash_attn_tc_kernel,
                         cudaFuncAttributeMaxDynamicSharedMemorySize, ATT_SMEM);
    dim3 fgrid(16, NHH, BB);   // 128-query tiles, heavy first
    flash_attn_tc_kernel<<<fgrid, 128, ATT_SMEM>>>(pQKVh, ids, pAOh);

    dim3 ogrid(HH / 128, MM / 128);   // (8, 32)
    gemm_f16_kernel<false, false, false><<<ogrid, 256, GEMM_SMEM>>>(
        pAOh, pWOh, bO, HH, out, nullptr);
}

// round 16
// speedup vs baseline: 1.0131x; 1.0131x over previous
#include <cuda_runtime.h>
#include <cuda_fp16.h>
#include <math.h>
#include <stdint.h>

// Problem constants
#define BB 2
#define SS 2048
#define HH 1024
#define NHH 16
#define MM (BB * SS)   // 4096
#define SQKV 3072

#define NEGF (-1e30f)
#define QSCALE 0.1803368801f   // 0.125 * log2(e)

// Scratch (device globals)
__device__ __half g_QKVh[MM * SQKV];
__device__ __half g_AOh[MM * HH];
__device__ __half g_Wqkvh[SQKV * HH];
__device__ __half g_WOh[HH * HH];
__device__ float  g_bqkv[SQKV];

// ---------------------------------------------------------------------------
// helpers
// ---------------------------------------------------------------------------
__device__ __forceinline__ uint32_t smem_u32(const void* p) {
    uint32_t a;
    asm("{ .reg .u64 t; cvta.to.shared.u64 t, %1; cvt.u32.u64 %0, t; }"
        : "=r"(a) : "l"(p));
    return a;
}

__device__ __forceinline__ void ldsm_x4(uint32_t* r, uint32_t addr) {
    asm volatile("ldmatrix.sync.aligned.m8n8.x4.shared.b16 {%0,%1,%2,%3}, [%4];"
                 : "=r"(r[0]), "=r"(r[1]), "=r"(r[2]), "=r"(r[3]) : "r"(addr));
}
__device__ __forceinline__ void ldsm_x4t(uint32_t* r, uint32_t addr) {
    asm volatile("ldmatrix.sync.aligned.m8n8.x4.trans.shared.b16 {%0,%1,%2,%3}, [%4];"
                 : "=r"(r[0]), "=r"(r[1]), "=r"(r[2]), "=r"(r[3]) : "r"(addr));
}
__device__ __forceinline__ void mma_f16(float* c, const uint32_t* a, const uint32_t* b) {
    asm volatile(
        "mma.sync.aligned.m16n8k16.row.col.f32.f16.f16.f32 "
        "{%0,%1,%2,%3}, {%4,%5,%6,%7}, {%8,%9}, {%0,%1,%2,%3};"
        : "+f"(c[0]), "+f"(c[1]), "+f"(c[2]), "+f"(c[3])
        : "r"(a[0]), "r"(a[1]), "r"(a[2]), "r"(a[3]), "r"(b[0]), "r"(b[1]));
}

#define CP16(smaddr, gptr) \
    asm volatile("cp.async.cg.shared.global [%0], [%1], 16;" \
                 :: "r"(smaddr), "l"(gptr) : "memory")
#define CP_COMMIT() asm volatile("cp.async.commit_group;" ::: "memory")
#define CP_WAIT1() asm volatile("cp.async.wait_group 1;" ::: "memory")
#define CP_WAIT0() asm volatile("cp.async.wait_group 0;" ::: "memory")

__device__ __forceinline__ uint32_t pack1(float x, float y) {
    __half2 h = __floats2half2_rn(x, y);
    return *(uint32_t*)&h;
}

// ---------------------------------------------------------------------------
// 4-way transpose 1024x1024 fp32 -> fp16, out[n][k] = W[k][n]; also packs
// the QKV bias vector (z<3 blocks copy their bias chunk).
// ---------------------------------------------------------------------------
__global__ __launch_bounds__(256) void transpose_half4(
    const float* __restrict__ W0, const float* __restrict__ W1,
    const float* __restrict__ W2, const float* __restrict__ W3,
    const float* __restrict__ b0, const float* __restrict__ b1,
    const float* __restrict__ b2,
    __half* __restrict__ qkvh, __half* __restrict__ woh,
    float* __restrict__ bqkv)
{
    __shared__ float t[32][33];
    const int z = blockIdx.z;
    const float* W = (z == 0) ? W0 : (z == 1) ? W1 : (z == 2) ? W2 : W3;
    __half* ho = (z < 3) ? qkvh + (size_t)z * HH * HH : woh;
    const int tid = threadIdx.y * 32 + threadIdx.x;

    if (z < 3 && blockIdx.x == 0 && blockIdx.y == 0) {
        const float* bz = (z == 0) ? b0 : (z == 1) ? b1 : b2;
        for (int i = tid; i < HH; i += 256) bqkv[z * HH + i] = bz[i];
    }

    int x = blockIdx.x * 32 + threadIdx.x;
    int y = blockIdx.y * 32 + threadIdx.y;
#pragma unroll
    for (int j = 0; j < 32; j += 8)
        t[threadIdx.y + j][threadIdx.x] = W[(size_t)(y + j) * HH + x];
    __syncthreads();
    x = blockIdx.y * 32 + threadIdx.x;
    y = blockIdx.x * 32 + threadIdx.y;
#pragma unroll
    for (int j = 0; j < 32; j += 8)
        ho[(size_t)(y + j) * HH + x] = __float2half_rn(t[threadIdx.x][threadIdx.y + j]);
}

// ---------------------------------------------------------------------------
// fp16 tensor-core GEMM: C[M=4096, NOUT] = A[M,1024] @ BT[NOUT,1024]^T + bias
// 3-stage cp.async ring with ONE barrier per chunk:
//   wait1 (chunk k done) -> syncthreads (frees stage computed at k-1)
//   -> issue chunk k+2 into that stage -> compute chunk k.
// ---------------------------------------------------------------------------
#define GK 1024
#define KC 32
#define LDAe 40
#define TILE_B (128 * LDAe * 2)
#define STAGE_B (2 * TILE_B)
#define GEMM_SMEM (3 * STAGE_B)   // 61440

template<bool HALF_OUT, bool QPRESCALE, bool A32>
__global__ __launch_bounds__(256, 2) void gemm_f16_kernel(
    const void* __restrict__ Ap, const __half* __restrict__ Bh,
    const float* __restrict__ bias, int NOUT, float* __restrict__ C,
    __half* __restrict__ Ch)
{
    extern __shared__ char sm[];
    const uint32_t sbase = smem_u32(sm);
    const int tid = threadIdx.x;
    const int wid = tid >> 5;
    const int lane = tid & 31;
    const int n0 = blockIdx.x * 128;
    const int m0 = blockIdx.y * 128;
    const int wm = (wid & 3) * 32;
    const int wn = (wid >> 2) * 64;

    const float* A32p = (const float*)Ap;
    const __half* A16p = (const __half*)Ap;

    float acc[2][8][4];
#pragma unroll
    for (int mi = 0; mi < 2; mi++)
#pragma unroll
        for (int ni = 0; ni < 8; ni++)
#pragma unroll
            for (int j = 0; j < 4; j++) acc[mi][ni][j] = 0.f;

    const int lr0 = tid >> 2;
    const int lc0 = tid & 3;

    float4 areg[2][2];

    auto ldgA = [&](int kc) {
        const int kk = kc * KC;
#pragma unroll
        for (int s = 0; s < 2; s++) {
            const int row = lr0 + s * 64;
            const float* p = A32p + (size_t)(m0 + row) * GK + kk + lc0 * 8;
            areg[s][0] = *(const float4*)p;
            areg[s][1] = *(const float4*)(p + 4);
        }
    };
    auto stsA = [&](int stage) {
#pragma unroll
        for (int s = 0; s < 2; s++) {
            const int row = lr0 + s * 64;
            uint4 v;
            v.x = pack1(areg[s][0].x, areg[s][0].y);
            v.y = pack1(areg[s][0].z, areg[s][0].w);
            v.z = pack1(areg[s][1].x, areg[s][1].y);
            v.w = pack1(areg[s][1].z, areg[s][1].w);
            *(uint4*)(sm + stage * STAGE_B + row * (LDAe * 2) + lc0 * 16) = v;
        }
    };
    auto cpB = [&](int kc, int stage) {
        const int kk = kc * KC;
        const uint32_t sb = sbase + stage * STAGE_B;
#pragma unroll
        for (int s = 0; s < 2; s++) {
            const int row = lr0 + s * 64;
            CP16(sb + TILE_B + (uint32_t)(row * (LDAe * 2) + lc0 * 16),
                 Bh + (size_t)(n0 + row) * GK + kk + lc0 * 8);
        }
    };
    auto cpA16 = [&](int kc, int stage) {
        const int kk = kc * KC;
        const uint32_t sb = sbase + stage * STAGE_B;
#pragma unroll
        for (int s = 0; s < 2; s++) {
            const int row = lr0 + s * 64;
            CP16(sb + (uint32_t)(row * (LDAe * 2) + lc0 * 16),
                 A16p + (size_t)(m0 + row) * GK + kk + lc0 * 8);
        }
    };

    const int NC = GK / KC;   // 32
    // prologue: fill stages 0 and 1; A regs prefetched for chunk 2
    if (A32) {
        ldgA(0); stsA(0); cpB(0, 0); CP_COMMIT();
        ldgA(1); stsA(1); cpB(1, 1); CP_COMMIT();
        ldgA(2);
    } else {
        cpA16(0, 0); cpB(0, 0); CP_COMMIT();
        cpA16(1, 1); cpB(1, 1); CP_COMMIT();
    }

    for (int kc = 0; kc < NC; kc++) {
        const int stage = kc % 3;
        if (kc + 1 < NC) CP_WAIT1();   // chunk kc complete (own thread)
        else             CP_WAIT0();
        __syncthreads();               // visibility + stage (kc+2)%3 is free

        if (kc + 2 < NC) {
            const int nst = (kc + 2) % 3;
            if (A32) {
                stsA(nst);             // areg holds chunk kc+2
                cpB(kc + 2, nst);
                CP_COMMIT();
                if (kc + 3 < NC) ldgA(kc + 3);
            } else {
                cpA16(kc + 2, nst);
                cpB(kc + 2, nst);
                CP_COMMIT();
            }
        }

        const uint32_t sb = sbase + stage * STAGE_B;
#pragma unroll
        for (int k16 = 0; k16 < KC; k16 += 16) {
            uint32_t ah[2][4];
#pragma unroll
            for (int mi = 0; mi < 2; mi++) {
                uint32_t addr = sb + 2u * (uint32_t)(
                    (wm + mi * 16 + (lane & 15)) * LDAe + k16 + 8 * (lane >> 4));
                ldsm_x4(ah[mi], addr);
            }
#pragma unroll
            for (int ni = 0; ni < 8; ni += 2) {
                const int mt = lane >> 3;
                const int rowB = wn + (ni + (mt >> 1)) * 8 + (lane & 7);
                uint32_t baddr = sb + TILE_B + 2u * (uint32_t)(
                    rowB * LDAe + k16 + 8 * (mt & 1));
                uint32_t bh[4];
                ldsm_x4(bh, baddr);
#pragma unroll
                for (int mi = 0; mi < 2; mi++) {
                    mma_f16(acc[mi][ni],     ah[mi], bh);
                    mma_f16(acc[mi][ni + 1], ah[mi], bh + 2);
                }
            }
        }
    }

#pragma unroll
    for (int mi = 0; mi < 2; mi++) {
#pragma unroll
        for (int ni = 0; ni < 8; ni++) {
            const int m = m0 + wm + mi * 16 + (lane >> 2);
            const int n = n0 + wn + ni * 8 + 2 * (lane & 3);
            const float b0 = bias[n], b1 = bias[n + 1];
            float sc = (QPRESCALE && n < 1024) ? QSCALE : 1.0f;
            float x0 = (acc[mi][ni][0] + b0) * sc, y0 = (acc[mi][ni][1] + b1) * sc;
            float x1 = (acc[mi][ni][2] + b0) * sc, y1 = (acc[mi][ni][3] + b1) * sc;
            if (HALF_OUT) {
                *(uint32_t*)(Ch + (size_t)m * NOUT + n) = pack1(x0, y0);
                *(uint32_t*)(Ch + (size_t)(m + 8) * NOUT + n) = pack1(x1, y1);
            } else {
                *(float2*)(C + (size_t)m * NOUT + n) = make_float2(x0, y0);
                *(float2*)(C + (size_t)(m + 8) * NOUT + n) = make_float2(x1, y1);
            }
        }
    }
}

// ---------------------------------------------------------------------------
// Tensor-core flash attention, fp16, static-max exp2 softmax.
// 128-thread CTA, 128-query tile, 32 q-rows/warp, 16-key chunks.
// 3-stage K/V ring with ONE barrier per tile; 3 CTAs/SM; mask-free fast path.
// ---------------------------------------------------------------------------
#define ARS 144                       // row stride bytes (64 halfs + 8 pad)
#define AKV (64 * ARS)                // 9216 per K or V tile
#define APADF (2 * AKV)               // pad floats at stage +18432
#define APFLG (APADF + 256)           // pad flag (int) per stage
#define AST_SZ (2 * AKV + 512)        // 18944
#define ATT_SMEM (3 * AST_SZ)         // 56832

__global__ __launch_bounds__(128, 3) void flash_attn_tc_kernel(
    const __half* __restrict__ QKVh, const int* __restrict__ ids,
    __half* __restrict__ AOh)
{
    extern __shared__ char sm[];
    const uint32_t sb = smem_u32(sm);
    const int tid = threadIdx.x;
    const int wid = tid >> 5;
    const int lane = tid & 31;
    const int qt = 15 - blockIdx.x;       // heavy tiles first
    const int q0 = qt * 128;
    const int h  = blockIdx.y;
    const int b  = blockIdx.z;
    const int wr = wid * 32;              // 32 q-rows per warp
    const int r4 = lane >> 2;
    const int c2 = lane & 3;

    // ---- load Q tile (128 rows) into smem (stage0+1 area), then to regs ----
    {
        const size_t qbase = (size_t)(b * SS + q0) * SQKV + h * 64;
#pragma unroll
        for (int i = 0; i < 8; i++) {
            int idx = tid + i * 128;
            int row = idx >> 3, c8 = idx & 7;
            CP16(sb + (uint32_t)(row * ARS + c8 * 16),
                 QKVh + qbase + (size_t)row * SQKV + c8 * 8);
        }
        CP_COMMIT();
    }
    CP_WAIT0();
    __syncthreads();

    uint32_t aq[2][4][4];   // [m-frag][k16][regs]
#pragma unroll
    for (int mi = 0; mi < 2; mi++) {
        const uint32_t abase = sb + (uint32_t)((wr + mi * 16 + (lane & 15)) * ARS
                                               + (lane >> 4) * 16);
#pragma unroll
        for (int k16 = 0; k16 < 4; k16++)
            ldsm_x4(aq[mi][k16], abase + k16 * 32);
    }
    __syncthreads();   // everyone done reading Q before K/V overwrite

    float* padp[3] = { (float*)(sm + APADF), (float*)(sm + AST_SZ + APADF),
                       (float*)(sm + 2 * AST_SZ + APADF) };
    int* flagp[3]  = { (int*)(sm + APFLG),   (int*)(sm + AST_SZ + APFLG),
                       (int*)(sm + 2 * AST_SZ + APFLG) };

    auto issue_tile = [&](int kt, int stage) {
        const int k0 = kt * 64;
        const uint32_t st = sb + stage * AST_SZ;
#pragma unroll
        for (int i = 0; i < 4; i++) {
            int idx = tid + i * 128;
            int row = idx >> 3, c8 = idx & 7;   // row 0..63
            uint32_t off = (uint32_t)(row * ARS + c8 * 16);
            size_t gk = (size_t)(b * SS + k0 + row) * SQKV + h * 64 + 1024 + c8 * 8;
            CP16(st + off,       QKVh + gk);           // K
            CP16(st + AKV + off, QKVh + gk + 1024);    // V
        }
        if (tid < 32) {  // single warp: race-free pad flag via ballot
            int p0 = (ids[b * SS + k0 + tid] == 0);
            int p1 = (ids[b * SS + k0 + 32 + tid] == 0);
            padp[stage][tid]      = p0 ? NEGF : 0.f;
            padp[stage][32 + tid] = p1 ? NEGF : 0.f;
            uint32_t any = __ballot_sync(0xffffffffu, p0 | p1);
            if (tid == 0) flagp[stage][0] = (any != 0);
        }
        CP_COMMIT();
    };

    const int qmax = q0 + wr + 31;        // warp's last q row
    const int nkt = 2 * qt + 2;           // 64-key tiles up to q0+127 (>= 2)

    issue_tile(0, 0);
    issue_tile(1, 1);

    float o[2][8][4];
#pragma unroll
    for (int mi = 0; mi < 2; mi++)
#pragma unroll
        for (int nb = 0; nb < 8; nb++)
#pragma unroll
            for (int j = 0; j < 4; j++) o[mi][nb][j] = 0.f;
    float lr[2][2] = {{0.f, 0.f}, {0.f, 0.f}};   // [m-frag][row-half]

    for (int kt = 0; kt < nkt; kt++) {
        const int stage = kt % 3;
        const int k0 = kt * 64;
        if (kt + 1 < nkt) CP_WAIT1();   // tile kt complete
        else              CP_WAIT0();
        __syncthreads();                // visibility + stage (kt+2)%3 free

        if (kt + 2 < nkt) issue_tile(kt + 2, (kt + 2) % 3);

        if (k0 <= qmax) {
            const uint32_t sth = sb + stage * AST_SZ;
            const float* padf = padp[stage];
            const bool haspad = (flagp[stage][0] != 0);
            const int mt = lane >> 3;

            // process 16-key chunks
#pragma unroll
            for (int c = 0; c < 4; c++) {
                const int k0c = k0 + c * 16;
                if (k0c > qmax) break;

                // ---- S chunk = Q K^T ----
                float s[2][2][4];
#pragma unroll
                for (int mi = 0; mi < 2; mi++)
#pragma unroll
                    for (int bbh = 0; bbh < 2; bbh++)
#pragma unroll
                        for (int j = 0; j < 4; j++) s[mi][bbh][j] = 0.f;

                const uint32_t bbase = sth + (uint32_t)(
                    (c * 16 + (mt >> 1) * 8 + (lane & 7)) * ARS + (mt & 1) * 16);
#pragma unroll
                for (int k16 = 0; k16 < 4; k16++) {
                    uint32_t bh[4];
                    ldsm_x4(bh, bbase + k16 * 32);
#pragma unroll
                    for (int mi = 0; mi < 2; mi++) {
                        mma_f16(s[mi][0], aq[mi][k16], bh);
                        mma_f16(s[mi][1], aq[mi][k16], bh + 2);
                    }
                }

                // ---- softmax: fast path (no mask) or full path ----
                const bool need_causal = (k0c + 15 > q0 + wr);
                if (!need_causal && !haspad) {
#pragma unroll
                    for (int mi = 0; mi < 2; mi++)
#pragma unroll
                        for (int bbh = 0; bbh < 2; bbh++) {
                            float v0 = exp2f(s[mi][bbh][0]);
                            float v1 = exp2f(s[mi][bbh][1]);
                            float v2 = exp2f(s[mi][bbh][2]);
                            float v3 = exp2f(s[mi][bbh][3]);
                            s[mi][bbh][0] = v0; s[mi][bbh][1] = v1;
                            s[mi][bbh][2] = v2; s[mi][bbh][3] = v3;
                            lr[mi][0] += v0 + v1;
                            lr[mi][1] += v2 + v3;
                        }
                } else {
#pragma unroll
                    for (int mi = 0; mi < 2; mi++) {
                        const int qg = q0 + wr + mi * 16 + r4;
#pragma unroll
                        for (int bbh = 0; bbh < 2; bbh++) {
                            const int col = c * 16 + bbh * 8 + 2 * c2;
                            const float p0 = padf[col], p1 = padf[col + 1];
                            float v0 = s[mi][bbh][0] + p0;
                            float v1 = s[mi][bbh][1] + p1;
                            float v2 = s[mi][bbh][2] + p0;
                            float v3 = s[mi][bbh][3] + p1;
                            if (need_causal) {
                                const int kg = k0 + col;
                                if (kg     > qg)     v0 = NEGF;
                                if (kg + 1 > qg)     v1 = NEGF;
                                if (kg     > qg + 8) v2 = NEGF;
                                if (kg + 1 > qg + 8) v3 = NEGF;
                            }
                            v0 = exp2f(v0); v1 = exp2f(v1);
                            v2 = exp2f(v2); v3 = exp2f(v3);
                            s[mi][bbh][0] = v0; s[mi][bbh][1] = v1;
                            s[mi][bbh][2] = v2; s[mi][bbh][3] = v3;
                            lr[mi][0] += v0 + v1;
                            lr[mi][1] += v2 + v3;
                        }
                    }
                }

                // ---- pack P ----
                uint32_t ph[2][4];
#pragma unroll
                for (int mi = 0; mi < 2; mi++) {
                    ph[mi][0] = pack1(s[mi][0][0], s[mi][0][1]);
                    ph[mi][1] = pack1(s[mi][0][2], s[mi][0][3]);
                    ph[mi][2] = pack1(s[mi][1][0], s[mi][1][1]);
                    ph[mi][3] = pack1(s[mi][1][2], s[mi][1][3]);
                }

                // ---- O += P V (chunk rows of V) ----
                const uint32_t vbase = sth + AKV + (uint32_t)(
                    (c * 16 + (lane & 15)) * ARS + (lane >> 4) * 16);
#pragma unroll
                for (int nb = 0; nb < 8; nb += 2) {
                    uint32_t vh_[4];
                    ldsm_x4t(vh_, vbase + (uint32_t)(nb * 16));
#pragma unroll
                    for (int mi = 0; mi < 2; mi++) {
                        mma_f16(o[mi][nb],     ph[mi], vh_);
                        mma_f16(o[mi][nb + 1], ph[mi], vh_ + 2);
                    }
                }
            }
        }
    }

    // ---- epilogue: reduce l across the 4-lane row group, normalize ----
#pragma unroll
    for (int mi = 0; mi < 2; mi++)
#pragma unroll
        for (int hh = 0; hh < 2; hh++)
#pragma unroll
            for (int off = 1; off < 4; off <<= 1)
                lr[mi][hh] += __shfl_xor_sync(0xffffffffu, lr[mi][hh], off);

#pragma unroll
    for (int mi = 0; mi < 2; mi++) {
        const float il0 = 1.f / lr[mi][0];
        const float il1 = 1.f / lr[mi][1];
        const int qg = q0 + wr + mi * 16 + r4;
        const size_t r0off = (size_t)(b * SS + qg) * HH + h * 64;
        const size_t r1off = r0off + (size_t)8 * HH;
#pragma unroll
        for (int nb = 0; nb < 8; nb++) {
            const int n = 8 * nb + 2 * c2;
            *(uint32_t*)(AOh + r0off + n) = pack1(o[mi][nb][0] * il0, o[mi][nb][1] * il0);
            *(uint32_t*)(AOh + r1off + n) = pack1(o[mi][nb][2] * il1, o[mi][nb][3] * il1);
        }
    }
}

// ---------------------------------------------------------------------------

extern "C" void kernel_launch(void* const* d_in, const int* in_sizes, int n_in,
                              void* d_out, int out_size)
{
    const float* X   = (const float*)d_in[0];
    const int*   ids = (const int*)d_in[1];
    const float* WQ  = (const float*)d_in[2];
    const float* WK  = (const float*)d_in[3];
    const float* WV  = (const float*)d_in[4];
    const float* bQ  = (const float*)d_in[5];
    const float* bK  = (const float*)d_in[6];
    const float* bV  = (const float*)d_in[7];
    const float* WO  = (const float*)d_in[8];
    const float* bO  = (const float*)d_in[9];
    float* out = (float*)d_out;

    __half *pQKVh, *pAOh, *pWqkvh, *pWOh;
    float* pbqkv;
    cudaGetSymbolAddress((void**)&pQKVh,  g_QKVh);
    cudaGetSymbolAddress((void**)&pAOh,   g_AOh);
    cudaGetSymbolAddress((void**)&pWqkvh, g_Wqkvh);
    cudaGetSymbolAddress((void**)&pWOh,   g_WOh);
    cudaGetSymbolAddress((void**)&pbqkv,  g_bqkv);

    dim3 tgrid(32, 32, 4), tblk(32, 8);
    transpose_half4<<<tgrid, tblk>>>(WQ, WK, WV, WO, bQ, bK, bV,
                                     pWqkvh, pWOh, pbqkv);

    cudaFuncSetAttribute((const void*)gemm_f16_kernel<true, true, true>,
                         cudaFuncAttributeMaxDynamicSharedMemorySize, GEMM_SMEM);
    cudaFuncSetAttribute((const void*)gemm_f16_kernel<false, false, false>,
                         cudaFuncAttributeMaxDynamicSharedMemorySize, GEMM_SMEM);

    dim3 qkvgrid(SQKV / 128, MM / 128);   // (24, 32)
    gemm_f16_kernel<true, true, true><<<qkvgrid, 256, GEMM_SMEM>>>(
        X, pWqkvh, pbqkv, SQKV, nullptr, pQKVh);

    cudaFuncSetAttribute(flash_attn_tc_kernel,
                         cudaFuncAttributeMaxDynamicSharedMemorySize, ATT_SMEM);
    dim3 fgrid(16, NHH, BB);   // 128-query tiles, heavy first
    flash_attn_tc_kernel<<<fgrid, 128, ATT_SMEM>>>(pQKVh, ids, pAOh);

    dim3 ogrid(HH / 128, MM / 128);   // (8, 32)
    gemm_f16_kernel<false, false, false><<<ogrid, 256, GEMM_SMEM>>>(
        pAOh, pWOh, bO, HH, out, nullptr);
}